// round 10
// baseline (speedup 1.0000x reference)
#include <cuda_runtime.h>
#include <cuda_fp16.h>
#include <cstdint>

#define VOCAB 100000
#define EMB   128
#define NTILES (VOCAB / 32)     // 3125 build tiles / flags
#define TOK_PER_WARP 8

// Scratch: vocab-major, bias-fused, L2-normalized table in FP16 (25.6 MB).
__device__ __half g_table[(size_t)VOCAB * EMB];

// Per-tile ready flags + reset counter. Zero at load; re-zeroed at the end of
// every gather run, so every call (and every graph replay) does identical work.
__device__ unsigned g_flags[NTILES];
__device__ unsigned g_done_ctr = 0;

// ---------------------------------------------------------------------------
// Kernel 1 (PDL primary): table[v][:] = (half) normalize(W[:, v] + b)
// One block per 32 vocab entries. Fires launch_dependents AT ENTRY so the
// gather grid starts while build is still running; per-tile flags provide the
// actual data dependency.
// ---------------------------------------------------------------------------
__global__ __launch_bounds__(256) void build_table_kernel(
        const float* __restrict__ W,
        const float* __restrict__ b) {
    // Let the dependent (gather) grid launch as early as possible.
    asm volatile("griddepcontrol.launch_dependents;" ::: "memory");

    __shared__ float tile[EMB][33];   // [j][v_local], pad -> conflict-free reduce

    const int v0   = blockIdx.x * 32;
    const int tid  = threadIdx.x;
    const int lane = tid & 31;
    const int wid  = tid >> 5;        // 0..7

    #pragma unroll
    for (int k = 0; k < 16; k++) {
        int j = k * 8 + wid;
        tile[j][lane] = W[(size_t)j * VOCAB + v0 + lane] + b[j];
    }
    __syncthreads();

    #pragma unroll
    for (int r = 0; r < 4; r++) {
        const int v = wid * 4 + r;

        float s = 0.f;
        #pragma unroll
        for (int k = 0; k < 4; k++) {
            float e = tile[lane + 32 * k][v];
            s += e * e;
        }
        #pragma unroll
        for (int o = 16; o > 0; o >>= 1)
            s += __shfl_xor_sync(0xFFFFFFFFu, s, o);

        const float inv = 1.0f / fmaxf(sqrtf(s), 1e-12f);

        __half2* dst = reinterpret_cast<__half2*>(g_table + (size_t)(v0 + v) * EMB);
        dst[lane]      = __floats2half2_rn(tile[2 * lane][v] * inv,
                                           tile[2 * lane + 1][v] * inv);
        dst[lane + 32] = __floats2half2_rn(tile[64 + 2 * lane][v] * inv,
                                           tile[64 + 2 * lane + 1][v] * inv);
    }

    // Doorbell: every thread fences its table stores, block syncs, then one
    // thread publishes the tile flag (fence -> sync -> store = release).
    __threadfence();
    __syncthreads();
    if (tid == 0)
        *(volatile unsigned*)&g_flags[blockIdx.x] = 1u;
}

// ---------------------------------------------------------------------------
// Kernel 2 (PDL secondary, no griddepcontrol.wait): gather-copy + widen,
// gated per-warp by the tile flags of the 8 rows it needs.
// ---------------------------------------------------------------------------
__global__ __launch_bounds__(256) void gather_kernel(
        const int* __restrict__ x,
        float* __restrict__ out,
        int n_tok,
        int n_blocks) {
    const int gwarp = (blockIdx.x * blockDim.x + threadIdx.x) >> 5;
    const int lane  = threadIdx.x & 31;
    const int t0    = gwarp * TOK_PER_WARP;

    if (t0 + TOK_PER_WARP <= n_tok) {
        int idx[TOK_PER_WARP];
        #pragma unroll
        for (int r = 0; r < TOK_PER_WARP; r++)
            idx[r] = __ldg(&x[t0 + r]);

        // Wait until the 8 tiles covering our rows are published.
        // Lane r (r<8) watches flag for token r; all lanes agree via __all.
        {
            const int my_tile = idx[lane & 7] >> 5;
            for (;;) {
                unsigned f = 1u;
                if (lane < TOK_PER_WARP)
                    f = *(volatile unsigned*)&g_flags[my_tile];
                if (__all_sync(0xFFFFFFFFu, f != 0u)) break;
                __nanosleep(40);
            }
            __threadfence();   // acquire: order table reads after flag reads
        }

        uint2 h[TOK_PER_WARP];
        #pragma unroll
        for (int r = 0; r < TOK_PER_WARP; r++)
            h[r] = __ldg(reinterpret_cast<const uint2*>(
                       g_table + (size_t)idx[r] * EMB) + lane);

        #pragma unroll
        for (int r = 0; r < TOK_PER_WARP; r++) {
            float2 f0 = __half22float2(*reinterpret_cast<__half2*>(&h[r].x));
            float2 f1 = __half22float2(*reinterpret_cast<__half2*>(&h[r].y));
            float4 o;
            o.x = f0.x; o.y = f0.y; o.z = f1.x; o.w = f1.y;
            __stcs(reinterpret_cast<float4*>(out + (size_t)(t0 + r) * EMB) + lane, o);
        }
    } else if (t0 < n_tok) {
        for (int t = t0; t < n_tok; t++) {
            const int idx = __ldg(&x[t]);
            while (*(volatile unsigned*)&g_flags[idx >> 5] == 0u)
                __nanosleep(40);
            __threadfence();
            uint2 h = __ldg(reinterpret_cast<const uint2*>(
                          g_table + (size_t)idx * EMB) + lane);
            float2 f0 = __half22float2(*reinterpret_cast<__half2*>(&h.x));
            float2 f1 = __half22float2(*reinterpret_cast<__half2*>(&h.y));
            float4 o;
            o.x = f0.x; o.y = f0.y; o.z = f1.x; o.w = f1.y;
            __stcs(reinterpret_cast<float4*>(out + (size_t)t * EMB) + lane, o);
        }
    }

    // ---- per-run flag reset: last block out zeroes flags + counter ----
    __shared__ int s_last;
    __syncthreads();
    if (threadIdx.x == 0) {
        unsigned old = atomicAdd(&g_done_ctr, 1u);
        s_last = (old == (unsigned)(n_blocks - 1));
    }
    __syncthreads();
    if (s_last) {
        for (int i = threadIdx.x; i < NTILES; i += blockDim.x)
            g_flags[i] = 0u;
        __syncthreads();
        if (threadIdx.x == 0) {
            __threadfence();
            g_done_ctr = 0u;
        }
    }
}

// ---------------------------------------------------------------------------
extern "C" void kernel_launch(void* const* d_in, const int* in_sizes, int n_in,
                              void* d_out, int out_size) {
    const int*   x = (const int*)d_in[0];    // [4096, 200] int32
    const float* W = (const float*)d_in[1];  // [128, 100000] fp32
    const float* b = (const float*)d_in[2];  // [128] fp32
    float* out = (float*)d_out;              // [4096, 200, 128] fp32

    const int n_tok = in_sizes[0];           // 819200

    build_table_kernel<<<NTILES, 256>>>(W, b);

    const int warps_needed = (n_tok + TOK_PER_WARP - 1) / TOK_PER_WARP;  // 102400
    const int blocks = (warps_needed + 7) / 8;                            // 12800

    // PDL secondary: launches while build is still in flight; per-tile flags
    // carry the data dependency (no griddepcontrol.wait on purpose).
    cudaLaunchConfig_t cfg = {};
    cfg.gridDim  = dim3(blocks, 1, 1);
    cfg.blockDim = dim3(256, 1, 1);
    cfg.dynamicSmemBytes = 0;
    cfg.stream = 0;
    cudaLaunchAttribute attr[1];
    attr[0].id = cudaLaunchAttributeProgrammaticStreamSerialization;
    attr[0].val.programmaticStreamSerializationAllowed = 1;
    cfg.attrs = attr;
    cfg.numAttrs = 1;
    cudaLaunchKernelEx(&cfg, gather_kernel, x, out, n_tok, blocks);
}

// round 11
// speedup vs baseline: 1.1210x; 1.1210x over previous
#include <cuda_runtime.h>
#include <cuda_fp16.h>
#include <cstdint>

#define VOCAB 100000
#define EMB   128

// Scratch: vocab-major, bias-fused, L2-normalized table in FP16.
// 100000 * 128 * 2B = 25.6 MB — firmly resident in GB300's ~126 MB L2.
__device__ __half g_table[(size_t)VOCAB * EMB];

// ---------------------------------------------------------------------------
// Kernel 1: table[v][:] = (half) normalize(W[:, v] + b)
// One block per 32 vocab entries, 256 threads.
// Loads from W are float4 (LDG.128): thread t, iter k handles float4-quad
// q = t + 256k -> row j = q/8, quad c = q%8 (8 float4 per 32-col j-row).
// 4 loads/thread instead of 16 scalar loads. Reduction path unchanged.
// ---------------------------------------------------------------------------
__global__ __launch_bounds__(256) void build_table_kernel(
        const float* __restrict__ W,
        const float* __restrict__ b) {
    __shared__ float tile[EMB][33];   // [j][v_local], pad 33 -> conflict-free reduce

    const int v0   = blockIdx.x * 32;
    const int tid  = threadIdx.x;
    const int lane = tid & 31;
    const int wid  = tid >> 5;        // 0..7

    // ---- vectorized load + bias: 1024 float4 total, 4 per thread ----
    const float4* W4 = reinterpret_cast<const float4*>(W);
    const int row_f4 = VOCAB / 4;             // 25000 float4 per j-row
    const int base_c = blockIdx.x * 8;        // v0/4

    float4 f[4];
    int jj[4], cc[4];
    #pragma unroll
    for (int k = 0; k < 4; k++) {
        int q = tid + k * 256;
        jj[k] = q >> 3;                       // 0..127
        cc[k] = q & 7;                        // 0..7
        f[k] = __ldg(&W4[(size_t)jj[k] * row_f4 + base_c + cc[k]]);
    }
    #pragma unroll
    for (int k = 0; k < 4; k++) {
        const float bj = __ldg(&b[jj[k]]);
        float* dst = &tile[jj[k]][cc[k] * 4];
        dst[0] = f[k].x + bj;
        dst[1] = f[k].y + bj;
        dst[2] = f[k].z + bj;
        dst[3] = f[k].w + bj;
    }
    __syncthreads();

    // ---- each warp normalizes 4 vocab rows, writes half2 (coalesced) ----
    #pragma unroll
    for (int r = 0; r < 4; r++) {
        const int v = wid * 4 + r;

        float s = 0.f;
        #pragma unroll
        for (int k = 0; k < 4; k++) {
            float e = tile[lane + 32 * k][v];
            s += e * e;
        }
        #pragma unroll
        for (int o = 16; o > 0; o >>= 1)
            s += __shfl_xor_sync(0xFFFFFFFFu, s, o);

        const float inv = 1.0f / fmaxf(sqrtf(s), 1e-12f);

        __half2* dst = reinterpret_cast<__half2*>(g_table + (size_t)(v0 + v) * EMB);
        dst[lane]      = __floats2half2_rn(tile[2 * lane][v] * inv,
                                           tile[2 * lane + 1][v] * inv);
        dst[lane + 32] = __floats2half2_rn(tile[64 + 2 * lane][v] * inv,
                                           tile[64 + 2 * lane + 1][v] * inv);
    }
}

// ---------------------------------------------------------------------------
// Kernel 2 (UNCHANGED from R3 — proven 68.2us, at the HBM write ceiling):
// gather-copy + fp16->fp32 widen. Warp handles 8 tokens; lane l moves 4
// halves of each row (256B coalesced read / 512B coalesced write per token).
// Output stores use evict-first (.cs) so the 419 MB stream doesn't evict the
// table from L2.
// ---------------------------------------------------------------------------
#define TOK_PER_WARP 8

__global__ __launch_bounds__(256) void gather_kernel(
        const int* __restrict__ x,
        float* __restrict__ out,
        int n_tok) {
    const int gwarp = (blockIdx.x * blockDim.x + threadIdx.x) >> 5;
    const int lane  = threadIdx.x & 31;
    const int t0    = gwarp * TOK_PER_WARP;
    if (t0 >= n_tok) return;

    if (t0 + TOK_PER_WARP <= n_tok) {
        int idx[TOK_PER_WARP];
        #pragma unroll
        for (int r = 0; r < TOK_PER_WARP; r++)
            idx[r] = __ldg(&x[t0 + r]);

        uint2 h[TOK_PER_WARP];
        #pragma unroll
        for (int r = 0; r < TOK_PER_WARP; r++)
            h[r] = __ldg(reinterpret_cast<const uint2*>(
                       g_table + (size_t)idx[r] * EMB) + lane);

        #pragma unroll
        for (int r = 0; r < TOK_PER_WARP; r++) {
            float2 f0 = __half22float2(*reinterpret_cast<__half2*>(&h[r].x));
            float2 f1 = __half22float2(*reinterpret_cast<__half2*>(&h[r].y));
            float4 o;
            o.x = f0.x; o.y = f0.y; o.z = f1.x; o.w = f1.y;
            __stcs(reinterpret_cast<float4*>(out + (size_t)(t0 + r) * EMB) + lane, o);
        }
    } else {
        for (int t = t0; t < n_tok; t++) {
            uint2 h = __ldg(reinterpret_cast<const uint2*>(
                          g_table + (size_t)__ldg(&x[t]) * EMB) + lane);
            float2 f0 = __half22float2(*reinterpret_cast<__half2*>(&h.x));
            float2 f1 = __half22float2(*reinterpret_cast<__half2*>(&h.y));
            float4 o;
            o.x = f0.x; o.y = f0.y; o.z = f1.x; o.w = f1.y;
            __stcs(reinterpret_cast<float4*>(out + (size_t)t * EMB) + lane, o);
        }
    }
}

// ---------------------------------------------------------------------------
extern "C" void kernel_launch(void* const* d_in, const int* in_sizes, int n_in,
                              void* d_out, int out_size) {
    const int*   x = (const int*)d_in[0];    // [4096, 200] int32
    const float* W = (const float*)d_in[1];  // [128, 100000] fp32
    const float* b = (const float*)d_in[2];  // [128] fp32
    float* out = (float*)d_out;              // [4096, 200, 128] fp32

    const int n_tok = in_sizes[0];           // 819200

    build_table_kernel<<<VOCAB / 32, 256>>>(W, b);

    const int warps_needed = (n_tok + TOK_PER_WARP - 1) / TOK_PER_WARP;  // 102400
    const int blocks = (warps_needed + 7) / 8;                            // 12800
    gather_kernel<<<blocks, 256>>>(x, out, n_tok);
}